// round 7
// baseline (speedup 1.0000x reference)
#include <cuda_runtime.h>
#include <cuda_fp16.h>
#include <cstdint>
#include <math.h>

// ---------------------------------------------------------------------------
// Problem constants
// ---------------------------------------------------------------------------
#define T_TOKENS 16384
#define H_DIM    2048
#define N_EXP    64
#define TOPK     8
#define KC       64                  // fp32 k-elements per chunk
#define NCHUNK   (H_DIM / KC)        // 32
#define BM       128                 // tokens per CTA
#define GAP_THR  2.5e-4f             // marginal-row flag threshold (abs logit)

// SMEM tile offsets (bytes). fp16 tiles, 128 B per row (64 halves), swizzled.
#define AHI_OFF  0                   // 128 x 64 fp16 = 16384 B
#define ALO_OFF  16384
#define BHI_OFF  32768               // 64 x 64 fp16 = 8192 B
#define BLO_OFF  40960
#define SMEM_TOTAL 49152             // also reused as logits smem [128][68] f32

// 16-byte-granule XOR swizzle within a 128-byte row
#define SWG(row, g) ((g) ^ ((row) & 7))

// Per-row "needs exact recompute" flags (written unconditionally every run).
__device__ unsigned char g_flags[T_TOKENS];

static __device__ __forceinline__ uint32_t smem_u32(const void* p) {
    uint32_t a;
    asm("{ .reg .u64 t; cvta.to.shared.u64 t, %1; cvt.u32.u64 %0, t; }"
        : "=r"(a) : "l"(p));
    return a;
}

static __device__ __forceinline__ void ldsm4(uint32_t r[4], uint32_t addr) {
    asm volatile("ldmatrix.sync.aligned.m8n8.x4.shared.b16 {%0,%1,%2,%3}, [%4];"
                 : "=r"(r[0]), "=r"(r[1]), "=r"(r[2]), "=r"(r[3]) : "r"(addr));
}

static __device__ __forceinline__ void mma16816(
    float c[4], const uint32_t a[4], uint32_t b0, uint32_t b1)
{
    asm volatile(
        "mma.sync.aligned.m16n8k16.row.col.f32.f16.f16.f32 "
        "{%0,%1,%2,%3}, {%4,%5,%6,%7}, {%8,%9}, {%0,%1,%2,%3};"
        : "+f"(c[0]), "+f"(c[1]), "+f"(c[2]), "+f"(c[3])
        : "r"(a[0]), "r"(a[1]), "r"(a[2]), "r"(a[3]), "r"(b0), "r"(b1));
}

// Split 8 fp32 into fp16 hi (16 B) and fp16 lo (16 B).
static __device__ __forceinline__ void cvt8(
    float4 p, float4 q, uint4& hi, uint4& lo)
{
    __half2 h0 = __floats2half2_rn(p.x, p.y);
    __half2 h1 = __floats2half2_rn(p.z, p.w);
    __half2 h2 = __floats2half2_rn(q.x, q.y);
    __half2 h3 = __floats2half2_rn(q.z, q.w);
    float2 f0 = __half22float2(h0), f1 = __half22float2(h1);
    float2 f2 = __half22float2(h2), f3 = __half22float2(h3);
    __half2 l0 = __floats2half2_rn(p.x - f0.x, p.y - f0.y);
    __half2 l1 = __floats2half2_rn(p.z - f1.x, p.w - f1.y);
    __half2 l2 = __floats2half2_rn(q.x - f2.x, q.y - f2.y);
    __half2 l3 = __floats2half2_rn(q.z - f3.x, q.w - f3.y);
    hi.x = *(uint32_t*)&h0; hi.y = *(uint32_t*)&h1;
    hi.z = *(uint32_t*)&h2; hi.w = *(uint32_t*)&h3;
    lo.x = *(uint32_t*)&l0; lo.y = *(uint32_t*)&l1;
    lo.z = *(uint32_t*)&l2; lo.w = *(uint32_t*)&l3;
}

// Shared top-8 + renormalized softmax writer (ties -> lower index).
static __device__ __forceinline__ void topk_and_write(
    const float* v_in, int row, float* vals, float* inds)
{
    float v[N_EXP];
#pragma unroll
    for (int j = 0; j < N_EXP; j++) v[j] = v_in[j];

    float tv[TOPK]; int ti[TOPK];
#pragma unroll
    for (int it = 0; it < TOPK; it++) {
        float bv = -INFINITY; int bi = 0;
#pragma unroll
        for (int j = 0; j < N_EXP; j++)
            if (v[j] > bv) { bv = v[j]; bi = j; }
        tv[it] = bv; ti[it] = bi;
        v[bi] = -INFINITY;
    }

    const float m = tv[0];
    float e[TOPK], s = 0.0f;
#pragma unroll
    for (int i = 0; i < TOPK; i++) { e[i] = expf(tv[i] - m); s += e[i]; }
    const float inv = 1.0f / s;

    *(float4*)(vals + (size_t)row * TOPK) =
        make_float4(e[0]*inv, e[1]*inv, e[2]*inv, e[3]*inv);
    *(float4*)(vals + (size_t)row * TOPK + 4) =
        make_float4(e[4]*inv, e[5]*inv, e[6]*inv, e[7]*inv);
    *(float4*)(inds + (size_t)row * TOPK) =
        make_float4((float)ti[0], (float)ti[1], (float)ti[2], (float)ti[3]);
    *(float4*)(inds + (size_t)row * TOPK + 4) =
        make_float4((float)ti[4], (float)ti[5], (float)ti[6], (float)ti[7]);
}

// ---------------------------------------------------------------------------
// Fused kernel: logits = A @ W^T via HMMA fp16 split (dual accumulators),
// + top-8 + renorm softmax + marginal-row flagging.
// ---------------------------------------------------------------------------
__global__ void __launch_bounds__(256, 1)
router_fused_kernel(const float* __restrict__ A,   // [T, H]
                    const float* __restrict__ W,   // [E, H]
                    float* __restrict__ logits,    // [T, E]
                    float* __restrict__ vals,      // [T, 8]
                    float* __restrict__ inds)      // [T, 8]
{
    extern __shared__ char smem[];
    const uint32_t sb = smem_u32(smem);
    const int tid  = threadIdx.x;
    const int wid  = tid >> 5;
    const int lane = tid & 31;
    const int blockRow = blockIdx.x * BM;
    const int mrow = wid * 16;          // warp's 16-row slice of the M tile

    float acc[8][4];     // hi*hi   (full magnitude)
    float acc2[8][4];    // hi*lo + lo*hi   (~2^-11 magnitude)
#pragma unroll
    for (int t = 0; t < 8; t++)
#pragma unroll
        for (int j = 0; j < 4; j++) { acc[t][j] = 0.0f; acc2[t][j] = 0.0f; }

    const float* Abase = A + (size_t)blockRow * H_DIM;

    float4 pa[4][2], pw[2][2];

    // ---- load chunk 0
    {
        const float* Ab = Abase;
        const float* Wb = W;
#pragma unroll
        for (int t = 0; t < 4; t++) {
            int i = tid + t * 256, row = i >> 3, g = i & 7;
            const float* p = Ab + (size_t)row * H_DIM + g * 8;
            pa[t][0] = *(const float4*)p;
            pa[t][1] = *(const float4*)(p + 4);
        }
#pragma unroll
        for (int t = 0; t < 2; t++) {
            int i = tid + t * 256, row = i >> 3, g = i & 7;
            const float* p = Wb + (size_t)row * H_DIM + g * 8;
            pw[t][0] = *(const float4*)p;
            pw[t][1] = *(const float4*)(p + 4);
        }
    }

    const int lj  = lane >> 3;
    const int lrr = lane & 7;
    const int jr  = (lj & 1) * 8 + lrr;
    const int jg  = lj >> 1;

    for (int c = 0; c < NCHUNK; c++) {
        // ---- convert + store current chunk to smem
#pragma unroll
        for (int t = 0; t < 4; t++) {
            int i = tid + t * 256, row = i >> 3, g = i & 7;
            uint4 hi, lo;
            cvt8(pa[t][0], pa[t][1], hi, lo);
            int off = row * 128 + SWG(row, g) * 16;
            *(uint4*)(smem + AHI_OFF + off) = hi;
            *(uint4*)(smem + ALO_OFF + off) = lo;
        }
#pragma unroll
        for (int t = 0; t < 2; t++) {
            int i = tid + t * 256, row = i >> 3, g = i & 7;
            uint4 hi, lo;
            cvt8(pw[t][0], pw[t][1], hi, lo);
            int off = row * 128 + SWG(row, g) * 16;
            *(uint4*)(smem + BHI_OFF + off) = hi;
            *(uint4*)(smem + BLO_OFF + off) = lo;
        }
        __syncthreads();

        // ---- issue next chunk's global loads (hidden under the MMA loop)
        if (c + 1 < NCHUNK) {
            const float* Ab = Abase + (c + 1) * KC;
            const float* Wb = W + (c + 1) * KC;
#pragma unroll
            for (int t = 0; t < 4; t++) {
                int i = tid + t * 256, row = i >> 3, g = i & 7;
                const float* p = Ab + (size_t)row * H_DIM + g * 8;
                pa[t][0] = *(const float4*)p;
                pa[t][1] = *(const float4*)(p + 4);
            }
#pragma unroll
            for (int t = 0; t < 2; t++) {
                int i = tid + t * 256, row = i >> 3, g = i & 7;
                const float* p = Wb + (size_t)row * H_DIM + g * 8;
                pw[t][0] = *(const float4*)p;
                pw[t][1] = *(const float4*)(p + 4);
            }
        }

        // ---- MMA over this chunk: 4 k16-steps
#pragma unroll
        for (int ks = 0; ks < 4; ks++) {
            const int gk = ks * 2;

            uint32_t ah[4], al[4];
            {
                int arow = mrow + jr;
                int ag   = gk + jg;
                uint32_t off = arow * 128 + SWG(arow, ag) * 16;
                ldsm4(ah, sb + AHI_OFF + off);
                ldsm4(al, sb + ALO_OFF + off);
            }

            uint32_t bh[8][2], bl[8][2];
#pragma unroll
            for (int p = 0; p < 4; p++) {
                int brow = p * 16 + jr;
                int bg   = gk + jg;
                uint32_t off = brow * 128 + SWG(brow, bg) * 16;
                uint32_t r[4];
                ldsm4(r, sb + BHI_OFF + off);
                bh[2*p][0] = r[0]; bh[2*p][1] = r[2];
                bh[2*p+1][0] = r[1]; bh[2*p+1][1] = r[3];
                ldsm4(r, sb + BLO_OFF + off);
                bl[2*p][0] = r[0]; bl[2*p][1] = r[2];
                bl[2*p+1][0] = r[1]; bl[2*p+1][1] = r[3];
            }

#pragma unroll
            for (int t = 0; t < 8; t++) {
                mma16816(acc[t],  ah, bh[t][0], bh[t][1]);   // hi*hi -> acc
                mma16816(acc2[t], ah, bl[t][0], bl[t][1]);   // hi*lo -> acc2
                mma16816(acc2[t], al, bh[t][0], bh[t][1]);   // lo*hi -> acc2
            }
        }
        __syncthreads();
    }

    // Fold the small-term accumulator in once.
#pragma unroll
    for (int t = 0; t < 8; t++)
#pragma unroll
        for (int j = 0; j < 4; j++) acc[t][j] += acc2[t][j];

    // ---------------- Epilogue ----------------
    float* lsm = (float*)smem;
    {
        const int group = lane >> 2, tig = lane & 3;
#pragma unroll
        for (int t = 0; t < 8; t++) {
            int col = t * 8 + 2 * tig;
            *(float2*)&lsm[(mrow + group)     * 68 + col] =
                make_float2(acc[t][0], acc[t][1]);
            *(float2*)&lsm[(mrow + group + 8) * 68 + col] =
                make_float2(acc[t][2], acc[t][3]);
        }
    }
    __syncthreads();

    // Coalesced logits store
#pragma unroll
    for (int t = 0; t < 8; t++) {
        int i = tid + t * 256;
        int row = i >> 4, q = i & 15;
        float4 v = *(float4*)&lsm[row * 68 + q * 4];
        *(float4*)&logits[(size_t)(blockRow + row) * N_EXP + q * 4] = v;
    }

    // Top-8 + renorm softmax + marginal-row flag: threads 0..127, one row each
    if (tid < BM) {
        const int row = blockRow + tid;
        float v[N_EXP];
#pragma unroll
        for (int j = 0; j < N_EXP; j++) v[j] = lsm[tid * 68 + j];

        float tv[TOPK + 1]; int ti[TOPK];
#pragma unroll
        for (int it = 0; it < TOPK; it++) {
            float bv = -INFINITY; int bi = 0;
#pragma unroll
            for (int j = 0; j < N_EXP; j++)
                if (v[j] > bv) { bv = v[j]; bi = j; }
            tv[it] = bv; ti[it] = bi;
            v[bi] = -INFINITY;
        }
        // 9th value for the boundary gap
        {
            float bv = -INFINITY;
#pragma unroll
            for (int j = 0; j < N_EXP; j++) bv = fmaxf(bv, v[j]);
            tv[TOPK] = bv;
        }

        float min_gap = INFINITY;
#pragma unroll
        for (int i = 0; i < TOPK; i++) min_gap = fminf(min_gap, tv[i] - tv[i + 1]);
        g_flags[row] = (min_gap < GAP_THR) ? 1 : 0;

        const float m = tv[0];
        float e[TOPK], s = 0.0f;
#pragma unroll
        for (int i = 0; i < TOPK; i++) { e[i] = expf(tv[i] - m); s += e[i]; }
        const float inv = 1.0f / s;

        *(float4*)(vals + (size_t)row * TOPK) =
            make_float4(e[0]*inv, e[1]*inv, e[2]*inv, e[3]*inv);
        *(float4*)(vals + (size_t)row * TOPK + 4) =
            make_float4(e[4]*inv, e[5]*inv, e[6]*inv, e[7]*inv);
        *(float4*)(inds + (size_t)row * TOPK) =
            make_float4((float)ti[0], (float)ti[1], (float)ti[2], (float)ti[3]);
        *(float4*)(inds + (size_t)row * TOPK + 4) =
            make_float4((float)ti[4], (float)ti[5], (float)ti[6], (float)ti[7]);
    }
}

// ---------------------------------------------------------------------------
// Repair kernel: recompute flagged rows with serial-in-k fp32 FMA
// (matches cublas-style accumulation order), redo top-8, overwrite outputs.
// One 64-thread block per token row; non-flagged blocks exit immediately.
// ---------------------------------------------------------------------------
__global__ void __launch_bounds__(64)
router_repair_kernel(const float* __restrict__ A,
                     const float* __restrict__ W,
                     float* __restrict__ logits,
                     float* __restrict__ vals,
                     float* __restrict__ inds)
{
    const int row = blockIdx.x;
    if (!g_flags[row]) return;

    __shared__ float slog[N_EXP];
    const int e = threadIdx.x;            // expert 0..63

    const float* a = A + (size_t)row * H_DIM;
    const float* w = W + (size_t)e * H_DIM;

    float s = 0.0f;
#pragma unroll 8
    for (int k = 0; k < H_DIM; k++)
        s = fmaf(__ldg(a + k), __ldg(w + k), s);

    slog[e] = s;
    logits[(size_t)row * N_EXP + e] = s;
    __syncthreads();

    if (e == 0)
        topk_and_write(slog, row, vals, inds);
}

// ---------------------------------------------------------------------------
// Launch
// ---------------------------------------------------------------------------
extern "C" void kernel_launch(void* const* d_in, const int* in_sizes, int n_in,
                              void* d_out, int out_size)
{
    const float* hidden = (const float*)d_in[0];   // [16384, 2048]
    const float* weight = (const float*)d_in[1];   // [64, 2048]
    float* out = (float*)d_out;

    float* logits = out;                                 // 16384*64
    float* vals   = out + (size_t)T_TOKENS * N_EXP;      // 16384*8
    float* inds   = vals + (size_t)T_TOKENS * TOPK;      // 16384*8

    cudaFuncSetAttribute(router_fused_kernel,
                         cudaFuncAttributeMaxDynamicSharedMemorySize, SMEM_TOTAL);
    router_fused_kernel<<<T_TOKENS / BM, 256, SMEM_TOTAL>>>(
        hidden, weight, logits, vals, inds);
    router_repair_kernel<<<T_TOKENS, 64>>>(
        hidden, weight, logits, vals, inds);
}

// round 8
// speedup vs baseline: 3.7501x; 3.7501x over previous
#include <cuda_runtime.h>
#include <cuda_fp16.h>
#include <cstdint>
#include <math.h>

// ---------------------------------------------------------------------------
// Problem constants
// ---------------------------------------------------------------------------
#define T_TOKENS 16384
#define H_DIM    2048
#define N_EXP    64
#define TOPK     8
#define KC       64                  // fp32 k-elements per chunk
#define NCHUNK   (H_DIM / KC)        // 32
#define BM       128                 // tokens per CTA
#define GAP_THR  3.0e-5f             // marginal-row flag threshold (abs logit)

// SMEM tile offsets (bytes). fp16 tiles, 128 B per row (64 halves), swizzled.
#define AHI_OFF  0                   // 128 x 64 fp16 = 16384 B
#define ALO_OFF  16384
#define BHI_OFF  32768               // 64 x 64 fp16 = 8192 B
#define BLO_OFF  40960
#define SMEM_TOTAL 49152             // also reused as logits smem [128][68] f32

// 16-byte-granule XOR swizzle within a 128-byte row
#define SWG(row, g) ((g) ^ ((row) & 7))

// Compacted list of marginal rows needing exact serial-fp32 recompute.
__device__ int g_count;
__device__ int g_list[T_TOKENS];

static __device__ __forceinline__ uint32_t smem_u32(const void* p) {
    uint32_t a;
    asm("{ .reg .u64 t; cvta.to.shared.u64 t, %1; cvt.u32.u64 %0, t; }"
        : "=r"(a) : "l"(p));
    return a;
}

static __device__ __forceinline__ void ldsm4(uint32_t r[4], uint32_t addr) {
    asm volatile("ldmatrix.sync.aligned.m8n8.x4.shared.b16 {%0,%1,%2,%3}, [%4];"
                 : "=r"(r[0]), "=r"(r[1]), "=r"(r[2]), "=r"(r[3]) : "r"(addr));
}

static __device__ __forceinline__ void mma16816(
    float c[4], const uint32_t a[4], uint32_t b0, uint32_t b1)
{
    asm volatile(
        "mma.sync.aligned.m16n8k16.row.col.f32.f16.f16.f32 "
        "{%0,%1,%2,%3}, {%4,%5,%6,%7}, {%8,%9}, {%0,%1,%2,%3};"
        : "+f"(c[0]), "+f"(c[1]), "+f"(c[2]), "+f"(c[3])
        : "r"(a[0]), "r"(a[1]), "r"(a[2]), "r"(a[3]), "r"(b0), "r"(b1));
}

// Split 8 fp32 into fp16 hi (16 B) and fp16 lo (16 B).
static __device__ __forceinline__ void cvt8(
    float4 p, float4 q, uint4& hi, uint4& lo)
{
    __half2 h0 = __floats2half2_rn(p.x, p.y);
    __half2 h1 = __floats2half2_rn(p.z, p.w);
    __half2 h2 = __floats2half2_rn(q.x, q.y);
    __half2 h3 = __floats2half2_rn(q.z, q.w);
    float2 f0 = __half22float2(h0), f1 = __half22float2(h1);
    float2 f2 = __half22float2(h2), f3 = __half22float2(h3);
    __half2 l0 = __floats2half2_rn(p.x - f0.x, p.y - f0.y);
    __half2 l1 = __floats2half2_rn(p.z - f1.x, p.w - f1.y);
    __half2 l2 = __floats2half2_rn(q.x - f2.x, q.y - f2.y);
    __half2 l3 = __floats2half2_rn(q.z - f3.x, q.w - f3.y);
    hi.x = *(uint32_t*)&h0; hi.y = *(uint32_t*)&h1;
    hi.z = *(uint32_t*)&h2; hi.w = *(uint32_t*)&h3;
    lo.x = *(uint32_t*)&l0; lo.y = *(uint32_t*)&l1;
    lo.z = *(uint32_t*)&l2; lo.w = *(uint32_t*)&l3;
}

// Shared top-8 + renormalized softmax writer (ties -> lower index).
static __device__ __forceinline__ void topk_and_write(
    const float* v_in, int row, float* vals, float* inds)
{
    float v[N_EXP];
#pragma unroll
    for (int j = 0; j < N_EXP; j++) v[j] = v_in[j];

    float tv[TOPK]; int ti[TOPK];
#pragma unroll
    for (int it = 0; it < TOPK; it++) {
        float bv = -INFINITY; int bi = 0;
#pragma unroll
        for (int j = 0; j < N_EXP; j++)
            if (v[j] > bv) { bv = v[j]; bi = j; }
        tv[it] = bv; ti[it] = bi;
        v[bi] = -INFINITY;
    }

    const float m = tv[0];
    float e[TOPK], s = 0.0f;
#pragma unroll
    for (int i = 0; i < TOPK; i++) { e[i] = expf(tv[i] - m); s += e[i]; }
    const float inv = 1.0f / s;

    *(float4*)(vals + (size_t)row * TOPK) =
        make_float4(e[0]*inv, e[1]*inv, e[2]*inv, e[3]*inv);
    *(float4*)(vals + (size_t)row * TOPK + 4) =
        make_float4(e[4]*inv, e[5]*inv, e[6]*inv, e[7]*inv);
    *(float4*)(inds + (size_t)row * TOPK) =
        make_float4((float)ti[0], (float)ti[1], (float)ti[2], (float)ti[3]);
    *(float4*)(inds + (size_t)row * TOPK + 4) =
        make_float4((float)ti[4], (float)ti[5], (float)ti[6], (float)ti[7]);
}

// ---------------------------------------------------------------------------
// Init: zero the marginal-row counter (runs every launch; deterministic).
// ---------------------------------------------------------------------------
__global__ void router_init_kernel() { g_count = 0; }

// ---------------------------------------------------------------------------
// Fused kernel: logits = A @ W^T via HMMA fp16 split (dual accumulators),
// + top-8 + renorm softmax + marginal-row flagging into compacted list.
// ---------------------------------------------------------------------------
__global__ void __launch_bounds__(256, 1)
router_fused_kernel(const float* __restrict__ A,   // [T, H]
                    const float* __restrict__ W,   // [E, H]
                    float* __restrict__ logits,    // [T, E]
                    float* __restrict__ vals,      // [T, 8]
                    float* __restrict__ inds)      // [T, 8]
{
    extern __shared__ char smem[];
    const uint32_t sb = smem_u32(smem);
    const int tid  = threadIdx.x;
    const int wid  = tid >> 5;
    const int lane = tid & 31;
    const int blockRow = blockIdx.x * BM;
    const int mrow = wid * 16;

    float acc[8][4];     // hi*hi   (full magnitude)
    float acc2[8][4];    // hi*lo + lo*hi   (~2^-11 magnitude)
#pragma unroll
    for (int t = 0; t < 8; t++)
#pragma unroll
        for (int j = 0; j < 4; j++) { acc[t][j] = 0.0f; acc2[t][j] = 0.0f; }

    const float* Abase = A + (size_t)blockRow * H_DIM;

    float4 pa[4][2], pw[2][2];

    // ---- load chunk 0
    {
        const float* Ab = Abase;
        const float* Wb = W;
#pragma unroll
        for (int t = 0; t < 4; t++) {
            int i = tid + t * 256, row = i >> 3, g = i & 7;
            const float* p = Ab + (size_t)row * H_DIM + g * 8;
            pa[t][0] = *(const float4*)p;
            pa[t][1] = *(const float4*)(p + 4);
        }
#pragma unroll
        for (int t = 0; t < 2; t++) {
            int i = tid + t * 256, row = i >> 3, g = i & 7;
            const float* p = Wb + (size_t)row * H_DIM + g * 8;
            pw[t][0] = *(const float4*)p;
            pw[t][1] = *(const float4*)(p + 4);
        }
    }

    const int lj  = lane >> 3;
    const int lrr = lane & 7;
    const int jr  = (lj & 1) * 8 + lrr;
    const int jg  = lj >> 1;

    for (int c = 0; c < NCHUNK; c++) {
        // ---- convert + store current chunk to smem
#pragma unroll
        for (int t = 0; t < 4; t++) {
            int i = tid + t * 256, row = i >> 3, g = i & 7;
            uint4 hi, lo;
            cvt8(pa[t][0], pa[t][1], hi, lo);
            int off = row * 128 + SWG(row, g) * 16;
            *(uint4*)(smem + AHI_OFF + off) = hi;
            *(uint4*)(smem + ALO_OFF + off) = lo;
        }
#pragma unroll
        for (int t = 0; t < 2; t++) {
            int i = tid + t * 256, row = i >> 3, g = i & 7;
            uint4 hi, lo;
            cvt8(pw[t][0], pw[t][1], hi, lo);
            int off = row * 128 + SWG(row, g) * 16;
            *(uint4*)(smem + BHI_OFF + off) = hi;
            *(uint4*)(smem + BLO_OFF + off) = lo;
        }
        __syncthreads();

        // ---- issue next chunk's global loads (hidden under the MMA loop)
        if (c + 1 < NCHUNK) {
            const float* Ab = Abase + (c + 1) * KC;
            const float* Wb = W + (c + 1) * KC;
#pragma unroll
            for (int t = 0; t < 4; t++) {
                int i = tid + t * 256, row = i >> 3, g = i & 7;
                const float* p = Ab + (size_t)row * H_DIM + g * 8;
                pa[t][0] = *(const float4*)p;
                pa[t][1] = *(const float4*)(p + 4);
            }
#pragma unroll
            for (int t = 0; t < 2; t++) {
                int i = tid + t * 256, row = i >> 3, g = i & 7;
                const float* p = Wb + (size_t)row * H_DIM + g * 8;
                pw[t][0] = *(const float4*)p;
                pw[t][1] = *(const float4*)(p + 4);
            }
        }

        // ---- MMA over this chunk: 4 k16-steps
#pragma unroll
        for (int ks = 0; ks < 4; ks++) {
            const int gk = ks * 2;

            uint32_t ah[4], al[4];
            {
                int arow = mrow + jr;
                int ag   = gk + jg;
                uint32_t off = arow * 128 + SWG(arow, ag) * 16;
                ldsm4(ah, sb + AHI_OFF + off);
                ldsm4(al, sb + ALO_OFF + off);
            }

            uint32_t bh[8][2], bl[8][2];
#pragma unroll
            for (int p = 0; p < 4; p++) {
                int brow = p * 16 + jr;
                int bg   = gk + jg;
                uint32_t off = brow * 128 + SWG(brow, bg) * 16;
                uint32_t r[4];
                ldsm4(r, sb + BHI_OFF + off);
                bh[2*p][0] = r[0]; bh[2*p][1] = r[2];
                bh[2*p+1][0] = r[1]; bh[2*p+1][1] = r[3];
                ldsm4(r, sb + BLO_OFF + off);
                bl[2*p][0] = r[0]; bl[2*p][1] = r[2];
                bl[2*p+1][0] = r[1]; bl[2*p+1][1] = r[3];
            }

#pragma unroll
            for (int t = 0; t < 8; t++) {
                mma16816(acc[t],  ah, bh[t][0], bh[t][1]);   // hi*hi -> acc
                mma16816(acc2[t], ah, bl[t][0], bl[t][1]);   // hi*lo -> acc2
                mma16816(acc2[t], al, bh[t][0], bh[t][1]);   // lo*hi -> acc2
            }
        }
        __syncthreads();
    }

    // Fold the small-term accumulator in once.
#pragma unroll
    for (int t = 0; t < 8; t++)
#pragma unroll
        for (int j = 0; j < 4; j++) acc[t][j] += acc2[t][j];

    // ---------------- Epilogue ----------------
    float* lsm = (float*)smem;
    {
        const int group = lane >> 2, tig = lane & 3;
#pragma unroll
        for (int t = 0; t < 8; t++) {
            int col = t * 8 + 2 * tig;
            *(float2*)&lsm[(mrow + group)     * 68 + col] =
                make_float2(acc[t][0], acc[t][1]);
            *(float2*)&lsm[(mrow + group + 8) * 68 + col] =
                make_float2(acc[t][2], acc[t][3]);
        }
    }
    __syncthreads();

    // Coalesced logits store
#pragma unroll
    for (int t = 0; t < 8; t++) {
        int i = tid + t * 256;
        int row = i >> 4, q = i & 15;
        float4 v = *(float4*)&lsm[row * 68 + q * 4];
        *(float4*)&logits[(size_t)(blockRow + row) * N_EXP + q * 4] = v;
    }

    // Top-8 + renorm softmax + marginal-row flag: threads 0..127, one row each
    if (tid < BM) {
        const int row = blockRow + tid;
        float v[N_EXP];
#pragma unroll
        for (int j = 0; j < N_EXP; j++) v[j] = lsm[tid * 68 + j];

        float tv[TOPK + 1]; int ti[TOPK];
#pragma unroll
        for (int it = 0; it < TOPK; it++) {
            float bv = -INFINITY; int bi = 0;
#pragma unroll
            for (int j = 0; j < N_EXP; j++)
                if (v[j] > bv) { bv = v[j]; bi = j; }
            tv[it] = bv; ti[it] = bi;
            v[bi] = -INFINITY;
        }
        // 9th value for the boundary gap
        {
            float bv = -INFINITY;
#pragma unroll
            for (int j = 0; j < N_EXP; j++) bv = fmaxf(bv, v[j]);
            tv[TOPK] = bv;
        }

        float min_gap = INFINITY;
#pragma unroll
        for (int i = 0; i < TOPK; i++) min_gap = fminf(min_gap, tv[i] - tv[i + 1]);
        if (min_gap < GAP_THR) {
            int idx = atomicAdd(&g_count, 1);
            g_list[idx] = row;
        }

        const float m = tv[0];
        float e[TOPK], s = 0.0f;
#pragma unroll
        for (int i = 0; i < TOPK; i++) { e[i] = expf(tv[i] - m); s += e[i]; }
        const float inv = 1.0f / s;

        *(float4*)(vals + (size_t)row * TOPK) =
            make_float4(e[0]*inv, e[1]*inv, e[2]*inv, e[3]*inv);
        *(float4*)(vals + (size_t)row * TOPK + 4) =
            make_float4(e[4]*inv, e[5]*inv, e[6]*inv, e[7]*inv);
        *(float4*)(inds + (size_t)row * TOPK) =
            make_float4((float)ti[0], (float)ti[1], (float)ti[2], (float)ti[3]);
        *(float4*)(inds + (size_t)row * TOPK + 4) =
            make_float4((float)ti[4], (float)ti[5], (float)ti[6], (float)ti[7]);
    }
}

// ---------------------------------------------------------------------------
// Repair kernel: recompute marginal rows with serial-in-k fp32 FMA
// (identical accumulation order: k = 0..2047 in sequence), coalesced via
// smem staging, 4 rows per block iteration over the compacted list.
// ---------------------------------------------------------------------------
__global__ void __launch_bounds__(64)
router_repair_kernel(const float* __restrict__ A,
                     const float* __restrict__ W,
                     float* __restrict__ logits,
                     float* __restrict__ vals,
                     float* __restrict__ inds)
{
    __shared__ float sw[N_EXP][129];    // padded: conflict-free column reads
    __shared__ float sa[4][128];
    __shared__ float slog[4][N_EXP];
    __shared__ int rows_s[4];

    const int tid = threadIdx.x;        // expert id
    const int count = g_count;
    const int ngroups = (count + 3) >> 2;

    for (int g = blockIdx.x; g < ngroups; g += gridDim.x) {
        if (tid < 4) {
            int i = g * 4 + tid;
            rows_s[tid] = (i < count) ? g_list[i] : -1;
        }
        __syncthreads();

        float acc0 = 0.0f, acc1 = 0.0f, acc2 = 0.0f, acc3 = 0.0f;

        for (int c = 0; c < 16; c++) {
            // W chunk: 64 rows x 128 floats, coalesced float4 loads
#pragma unroll
            for (int j = 0; j < 32; j++) {
                int i = tid + 64 * j;
                int row = i >> 5, q = i & 31;
                float4 v = *(const float4*)(W + (size_t)row * H_DIM + c * 128 + q * 4);
                sw[row][q*4+0] = v.x; sw[row][q*4+1] = v.y;
                sw[row][q*4+2] = v.z; sw[row][q*4+3] = v.w;
            }
            // A chunks for up to 4 rows
#pragma unroll
            for (int j = 0; j < 2; j++) {
                int i = tid + 64 * j;
                int rr = i >> 5, q = i & 31;
                int row = rows_s[rr];
                if (row >= 0) {
                    float4 v = *(const float4*)(A + (size_t)row * H_DIM + c * 128 + q * 4);
                    sa[rr][q*4+0] = v.x; sa[rr][q*4+1] = v.y;
                    sa[rr][q*4+2] = v.z; sa[rr][q*4+3] = v.w;
                }
            }
            __syncthreads();

#pragma unroll 16
            for (int k = 0; k < 128; k++) {
                float w = sw[tid][k];
                acc0 = fmaf(sa[0][k], w, acc0);
                acc1 = fmaf(sa[1][k], w, acc1);
                acc2 = fmaf(sa[2][k], w, acc2);
                acc3 = fmaf(sa[3][k], w, acc3);
            }
            __syncthreads();
        }

        slog[0][tid] = acc0; slog[1][tid] = acc1;
        slog[2][tid] = acc2; slog[3][tid] = acc3;
#pragma unroll
        for (int rr = 0; rr < 4; rr++) {
            int row = rows_s[rr];
            if (row >= 0)
                logits[(size_t)row * N_EXP + tid] = slog[rr][tid];
        }
        __syncthreads();

        if (tid < 4 && rows_s[tid] >= 0)
            topk_and_write(slog[tid], rows_s[tid], vals, inds);
        __syncthreads();
    }
}

// ---------------------------------------------------------------------------
// Launch
// ---------------------------------------------------------------------------
extern "C" void kernel_launch(void* const* d_in, const int* in_sizes, int n_in,
                              void* d_out, int out_size)
{
    const float* hidden = (const float*)d_in[0];   // [16384, 2048]
    const float* weight = (const float*)d_in[1];   // [64, 2048]
    float* out = (float*)d_out;

    float* logits = out;                                 // 16384*64
    float* vals   = out + (size_t)T_TOKENS * N_EXP;      // 16384*8
    float* inds   = vals + (size_t)T_TOKENS * TOPK;      // 16384*8

    router_init_kernel<<<1, 1>>>();

    cudaFuncSetAttribute(router_fused_kernel,
                         cudaFuncAttributeMaxDynamicSharedMemorySize, SMEM_TOTAL);
    router_fused_kernel<<<T_TOKENS / BM, 256, SMEM_TOTAL>>>(
        hidden, weight, logits, vals, inds);

    router_repair_kernel<<<256, 64>>>(
        hidden, weight, logits, vals, inds);
}

// round 9
// speedup vs baseline: 3.8361x; 1.0230x over previous
#include <cuda_runtime.h>
#include <cuda_fp16.h>
#include <cstdint>
#include <math.h>

// ---------------------------------------------------------------------------
// Problem constants
// ---------------------------------------------------------------------------
#define T_TOKENS 16384
#define H_DIM    2048
#define N_EXP    64
#define TOPK     8
#define KC       64                  // fp32 k-elements per chunk
#define NCHUNK   (H_DIM / KC)        // 32
#define BM       128                 // tokens per CTA
#define GAP_THR  3.0e-5f             // marginal-row flag threshold (abs logit)

// SMEM: double-buffered fp16 tiles, 128 B per row (64 halves), swizzled.
//   per buffer: A_hi 16K | A_lo 16K | B_hi 8K | B_lo 8K = 48 KB
#define BUFSZ    49152
#define AHI_OFF(b)  ((b) * BUFSZ + 0)
#define ALO_OFF(b)  ((b) * BUFSZ + 16384)
#define BHI_OFF(b)  ((b) * BUFSZ + 32768)
#define BLO_OFF(b)  ((b) * BUFSZ + 40960)
#define SMEM_TOTAL  (2 * BUFSZ)      // 98304; epilogue reuses [0,34816) as f32

// 16-byte-granule XOR swizzle within a 128-byte row
#define SWG(row, g) ((g) ^ ((row) & 7))

// Compacted list of marginal rows needing exact serial-fp32 recompute.
// Zero-initialized at module load; repair kernel resets them at exit so the
// zero-at-entry invariant holds across graph replays.
__device__ int g_count;
__device__ int g_done;
__device__ int g_list[T_TOKENS];

static __device__ __forceinline__ uint32_t smem_u32(const void* p) {
    uint32_t a;
    asm("{ .reg .u64 t; cvta.to.shared.u64 t, %1; cvt.u32.u64 %0, t; }"
        : "=r"(a) : "l"(p));
    return a;
}

static __device__ __forceinline__ void ldsm4(uint32_t r[4], uint32_t addr) {
    asm volatile("ldmatrix.sync.aligned.m8n8.x4.shared.b16 {%0,%1,%2,%3}, [%4];"
                 : "=r"(r[0]), "=r"(r[1]), "=r"(r[2]), "=r"(r[3]) : "r"(addr));
}

static __device__ __forceinline__ void mma16816(
    float c[4], const uint32_t a[4], uint32_t b0, uint32_t b1)
{
    asm volatile(
        "mma.sync.aligned.m16n8k16.row.col.f32.f16.f16.f32 "
        "{%0,%1,%2,%3}, {%4,%5,%6,%7}, {%8,%9}, {%0,%1,%2,%3};"
        : "+f"(c[0]), "+f"(c[1]), "+f"(c[2]), "+f"(c[3])
        : "r"(a[0]), "r"(a[1]), "r"(a[2]), "r"(a[3]), "r"(b0), "r"(b1));
}

// Split 8 fp32 into fp16 hi (16 B) and fp16 lo (16 B).
static __device__ __forceinline__ void cvt8(
    float4 p, float4 q, uint4& hi, uint4& lo)
{
    __half2 h0 = __floats2half2_rn(p.x, p.y);
    __half2 h1 = __floats2half2_rn(p.z, p.w);
    __half2 h2 = __floats2half2_rn(q.x, q.y);
    __half2 h3 = __floats2half2_rn(q.z, q.w);
    float2 f0 = __half22float2(h0), f1 = __half22float2(h1);
    float2 f2 = __half22float2(h2), f3 = __half22float2(h3);
    __half2 l0 = __floats2half2_rn(p.x - f0.x, p.y - f0.y);
    __half2 l1 = __floats2half2_rn(p.z - f1.x, p.w - f1.y);
    __half2 l2 = __floats2half2_rn(q.x - f2.x, q.y - f2.y);
    __half2 l3 = __floats2half2_rn(q.z - f3.x, q.w - f3.y);
    hi.x = *(uint32_t*)&h0; hi.y = *(uint32_t*)&h1;
    hi.z = *(uint32_t*)&h2; hi.w = *(uint32_t*)&h3;
    lo.x = *(uint32_t*)&l0; lo.y = *(uint32_t*)&l1;
    lo.z = *(uint32_t*)&l2; lo.w = *(uint32_t*)&l3;
}

// Shared top-8 + renormalized softmax writer (ties -> lower index).
static __device__ __forceinline__ void topk_and_write(
    const float* v_in, int row, float* vals, float* inds)
{
    float v[N_EXP];
#pragma unroll
    for (int j = 0; j < N_EXP; j++) v[j] = v_in[j];

    float tv[TOPK]; int ti[TOPK];
#pragma unroll
    for (int it = 0; it < TOPK; it++) {
        float bv = -INFINITY; int bi = 0;
#pragma unroll
        for (int j = 0; j < N_EXP; j++)
            if (v[j] > bv) { bv = v[j]; bi = j; }
        tv[it] = bv; ti[it] = bi;
        v[bi] = -INFINITY;
    }

    const float m = tv[0];
    float e[TOPK], s = 0.0f;
#pragma unroll
    for (int i = 0; i < TOPK; i++) { e[i] = expf(tv[i] - m); s += e[i]; }
    const float inv = 1.0f / s;

    *(float4*)(vals + (size_t)row * TOPK) =
        make_float4(e[0]*inv, e[1]*inv, e[2]*inv, e[3]*inv);
    *(float4*)(vals + (size_t)row * TOPK + 4) =
        make_float4(e[4]*inv, e[5]*inv, e[6]*inv, e[7]*inv);
    *(float4*)(inds + (size_t)row * TOPK) =
        make_float4((float)ti[0], (float)ti[1], (float)ti[2], (float)ti[3]);
    *(float4*)(inds + (size_t)row * TOPK + 4) =
        make_float4((float)ti[4], (float)ti[5], (float)ti[6], (float)ti[7]);
}

// ---------------------------------------------------------------------------
// Fused kernel: logits = A @ W^T via HMMA fp16 split (dual accumulators),
// double-buffered smem, 1 sync per chunk, + top-8 + flagging.
// ---------------------------------------------------------------------------
__global__ void __launch_bounds__(256, 1)
router_fused_kernel(const float* __restrict__ A,   // [T, H]
                    const float* __restrict__ W,   // [E, H]
                    float* __restrict__ logits,    // [T, E]
                    float* __restrict__ vals,      // [T, 8]
                    float* __restrict__ inds)      // [T, 8]
{
    extern __shared__ char smem[];
    const uint32_t sb = smem_u32(smem);
    const int tid  = threadIdx.x;
    const int wid  = tid >> 5;
    const int lane = tid & 31;
    const int blockRow = blockIdx.x * BM;
    const int mrow = wid * 16;

    float acc[8][4];     // hi*hi   (full magnitude)
    float acc2[8][4];    // hi*lo + lo*hi   (~2^-11 magnitude)
#pragma unroll
    for (int t = 0; t < 8; t++)
#pragma unroll
        for (int j = 0; j < 4; j++) { acc[t][j] = 0.0f; acc2[t][j] = 0.0f; }

    const float* Abase = A + (size_t)blockRow * H_DIM;

    // Cooperative-load index decomposition (same for all chunks)
    const int ldRowA[4] = { (tid + 0*256) >> 3, (tid + 1*256) >> 3,
                            (tid + 2*256) >> 3, (tid + 3*256) >> 3 };
    const int ldG = tid & 7;

    float4 pa[4][2], pw[2][2];

    // ---- prologue: LDG chunk 0, convert+store into buffer 0
#pragma unroll
    for (int t = 0; t < 4; t++) {
        const float* p = Abase + (size_t)ldRowA[t] * H_DIM + ldG * 8;
        pa[t][0] = *(const float4*)p;
        pa[t][1] = *(const float4*)(p + 4);
    }
#pragma unroll
    for (int t = 0; t < 2; t++) {
        int row = (tid + t * 256) >> 3;
        const float* p = W + (size_t)row * H_DIM + ldG * 8;
        pw[t][0] = *(const float4*)p;
        pw[t][1] = *(const float4*)(p + 4);
    }
#pragma unroll
    for (int t = 0; t < 4; t++) {
        uint4 hi, lo;
        cvt8(pa[t][0], pa[t][1], hi, lo);
        int off = ldRowA[t] * 128 + SWG(ldRowA[t], ldG) * 16;
        *(uint4*)(smem + AHI_OFF(0) + off) = hi;
        *(uint4*)(smem + ALO_OFF(0) + off) = lo;
    }
#pragma unroll
    for (int t = 0; t < 2; t++) {
        int row = (tid + t * 256) >> 3;
        uint4 hi, lo;
        cvt8(pw[t][0], pw[t][1], hi, lo);
        int off = row * 128 + SWG(row, ldG) * 16;
        *(uint4*)(smem + BHI_OFF(0) + off) = hi;
        *(uint4*)(smem + BLO_OFF(0) + off) = lo;
    }

    const int lj  = lane >> 3;
    const int lrr = lane & 7;
    const int jr  = (lj & 1) * 8 + lrr;
    const int jg  = lj >> 1;

    for (int c = 0; c < NCHUNK; c++) {
        const int buf = c & 1;

        // ---- issue next chunk's global loads (consumed after MMA)
        if (c + 1 < NCHUNK) {
            const float* Ab = Abase + (c + 1) * KC;
            const float* Wb = W + (c + 1) * KC;
#pragma unroll
            for (int t = 0; t < 4; t++) {
                const float* p = Ab + (size_t)ldRowA[t] * H_DIM + ldG * 8;
                pa[t][0] = *(const float4*)p;
                pa[t][1] = *(const float4*)(p + 4);
            }
#pragma unroll
            for (int t = 0; t < 2; t++) {
                int row = (tid + t * 256) >> 3;
                const float* p = Wb + (size_t)row * H_DIM + ldG * 8;
                pw[t][0] = *(const float4*)p;
                pw[t][1] = *(const float4*)(p + 4);
            }
        }

        __syncthreads();   // all warps' stores into buf are complete

        // ---- MMA over buf: 4 k16-steps
#pragma unroll
        for (int ks = 0; ks < 4; ks++) {
            const int gk = ks * 2;

            uint32_t ah[4], al[4];
            {
                int arow = mrow + jr;
                int ag   = gk + jg;
                uint32_t off = arow * 128 + SWG(arow, ag) * 16;
                ldsm4(ah, sb + AHI_OFF(buf) + off);
                ldsm4(al, sb + ALO_OFF(buf) + off);
            }

            uint32_t bh[8][2], bl[8][2];
#pragma unroll
            for (int p = 0; p < 4; p++) {
                int brow = p * 16 + jr;
                int bg   = gk + jg;
                uint32_t off = brow * 128 + SWG(brow, bg) * 16;
                uint32_t r[4];
                ldsm4(r, sb + BHI_OFF(buf) + off);
                bh[2*p][0] = r[0]; bh[2*p][1] = r[2];
                bh[2*p+1][0] = r[1]; bh[2*p+1][1] = r[3];
                ldsm4(r, sb + BLO_OFF(buf) + off);
                bl[2*p][0] = r[0]; bl[2*p][1] = r[2];
                bl[2*p+1][0] = r[1]; bl[2*p+1][1] = r[3];
            }

#pragma unroll
            for (int t = 0; t < 8; t++) {
                mma16816(acc[t],  ah, bh[t][0], bh[t][1]);   // hi*hi -> acc
                mma16816(acc2[t], ah, bl[t][0], bl[t][1]);   // hi*lo -> acc2
                mma16816(acc2[t], al, bh[t][0], bh[t][1]);   // lo*hi -> acc2
            }
        }

        // ---- convert + store next chunk into the other buffer
        if (c + 1 < NCHUNK) {
            const int nbuf = buf ^ 1;
#pragma unroll
            for (int t = 0; t < 4; t++) {
                uint4 hi, lo;
                cvt8(pa[t][0], pa[t][1], hi, lo);
                int off = ldRowA[t] * 128 + SWG(ldRowA[t], ldG) * 16;
                *(uint4*)(smem + AHI_OFF(nbuf) + off) = hi;
                *(uint4*)(smem + ALO_OFF(nbuf) + off) = lo;
            }
#pragma unroll
            for (int t = 0; t < 2; t++) {
                int row = (tid + t * 256) >> 3;
                uint4 hi, lo;
                cvt8(pw[t][0], pw[t][1], hi, lo);
                int off = row * 128 + SWG(row, ldG) * 16;
                *(uint4*)(smem + BHI_OFF(nbuf) + off) = hi;
                *(uint4*)(smem + BLO_OFF(nbuf) + off) = lo;
            }
        }
    }

    // Fold the small-term accumulator in once.
#pragma unroll
    for (int t = 0; t < 8; t++)
#pragma unroll
        for (int j = 0; j < 4; j++) acc[t][j] += acc2[t][j];

    __syncthreads();   // all warps done with the final MMA buffer

    // ---------------- Epilogue ----------------
    float* lsm = (float*)smem;   // [128][68] f32 (34816 B)
    {
        const int group = lane >> 2, tig = lane & 3;
#pragma unroll
        for (int t = 0; t < 8; t++) {
            int col = t * 8 + 2 * tig;
            *(float2*)&lsm[(mrow + group)     * 68 + col] =
                make_float2(acc[t][0], acc[t][1]);
            *(float2*)&lsm[(mrow + group + 8) * 68 + col] =
                make_float2(acc[t][2], acc[t][3]);
        }
    }
    __syncthreads();

    // Coalesced logits store
#pragma unroll
    for (int t = 0; t < 8; t++) {
        int i = tid + t * 256;
        int row = i >> 4, q = i & 15;
        float4 v = *(float4*)&lsm[row * 68 + q * 4];
        *(float4*)&logits[(size_t)(blockRow + row) * N_EXP + q * 4] = v;
    }

    // Top-8 + renorm softmax + marginal-row flag: threads 0..127, one row each
    if (tid < BM) {
        const int row = blockRow + tid;
        float v[N_EXP];
#pragma unroll
        for (int j = 0; j < N_EXP; j++) v[j] = lsm[tid * 68 + j];

        float tv[TOPK + 1]; int ti[TOPK];
#pragma unroll
        for (int it = 0; it < TOPK; it++) {
            float bv = -INFINITY; int bi = 0;
#pragma unroll
            for (int j = 0; j < N_EXP; j++)
                if (v[j] > bv) { bv = v[j]; bi = j; }
            tv[it] = bv; ti[it] = bi;
            v[bi] = -INFINITY;
        }
        {
            float bv = -INFINITY;
#pragma unroll
            for (int j = 0; j < N_EXP; j++) bv = fmaxf(bv, v[j]);
            tv[TOPK] = bv;
        }

        float min_gap = INFINITY;
#pragma unroll
        for (int i = 0; i < TOPK; i++) min_gap = fminf(min_gap, tv[i] - tv[i + 1]);
        if (min_gap < GAP_THR) {
            int idx = atomicAdd(&g_count, 1);
            g_list[idx] = row;
        }

        const float m = tv[0];
        float e[TOPK], s = 0.0f;
#pragma unroll
        for (int i = 0; i < TOPK; i++) { e[i] = expf(tv[i] - m); s += e[i]; }
        const float inv = 1.0f / s;

        *(float4*)(vals + (size_t)row * TOPK) =
            make_float4(e[0]*inv, e[1]*inv, e[2]*inv, e[3]*inv);
        *(float4*)(vals + (size_t)row * TOPK + 4) =
            make_float4(e[4]*inv, e[5]*inv, e[6]*inv, e[7]*inv);
        *(float4*)(inds + (size_t)row * TOPK) =
            make_float4((float)ti[0], (float)ti[1], (float)ti[2], (float)ti[3]);
        *(float4*)(inds + (size_t)row * TOPK + 4) =
            make_float4((float)ti[4], (float)ti[5], (float)ti[6], (float)ti[7]);
    }
}

// ---------------------------------------------------------------------------
// Repair kernel: recompute marginal rows with serial-in-k fp32 FMA
// (identical accumulation order: k = 0..2047), coalesced via smem staging,
// 4 rows per block group over the compacted list. The last block to finish
// resets g_count/g_done so the next graph replay starts from zero.
// ---------------------------------------------------------------------------
__global__ void __launch_bounds__(64)
router_repair_kernel(const float* __restrict__ A,
                     const float* __restrict__ W,
                     float* __restrict__ logits,
                     float* __restrict__ vals,
                     float* __restrict__ inds)
{
    __shared__ float sw[N_EXP][129];    // padded: conflict-free column reads
    __shared__ float sa[4][128];
    __shared__ float slog[4][N_EXP];
    __shared__ int rows_s[4];

    const int tid = threadIdx.x;        // expert id
    const int count = g_count;
    const int ngroups = (count + 3) >> 2;

    for (int g = blockIdx.x; g < ngroups; g += gridDim.x) {
        if (tid < 4) {
            int i = g * 4 + tid;
            rows_s[tid] = (i < count) ? g_list[i] : -1;
        }
        __syncthreads();

        float acc0 = 0.0f, acc1 = 0.0f, acc2 = 0.0f, acc3 = 0.0f;

        for (int c = 0; c < 16; c++) {
#pragma unroll
            for (int j = 0; j < 32; j++) {
                int i = tid + 64 * j;
                int row = i >> 5, q = i & 31;
                float4 v = *(const float4*)(W + (size_t)row * H_DIM + c * 128 + q * 4);
                sw[row][q*4+0] = v.x; sw[row][q*4+1] = v.y;
                sw[row][q*4+2] = v.z; sw[row][q*4+3] = v.w;
            }
#pragma unroll
            for (int j = 0; j < 2; j++) {
                int i = tid + 64 * j;
                int rr = i >> 5, q = i & 31;
                int row = rows_s[rr];
                if (row >= 0) {
                    float4 v = *(const float4*)(A + (size_t)row * H_DIM + c * 128 + q * 4);
                    sa[rr][q*4+0] = v.x; sa[rr][q*4+1] = v.y;
                    sa[rr][q*4+2] = v.z; sa[rr][q*4+3] = v.w;
                }
            }
            __syncthreads();

#pragma unroll 16
            for (int k = 0; k < 128; k++) {
                float w = sw[tid][k];
                acc0 = fmaf(sa[0][k], w, acc0);
                acc1 = fmaf(sa[1][k], w, acc1);
                acc2 = fmaf(sa[2][k], w, acc2);
                acc3 = fmaf(sa[3][k], w, acc3);
            }
            __syncthreads();
        }

        slog[0][tid] = acc0; slog[1][tid] = acc1;
        slog[2][tid] = acc2; slog[3][tid] = acc3;
#pragma unroll
        for (int rr = 0; rr < 4; rr++) {
            int row = rows_s[rr];
            if (row >= 0)
                logits[(size_t)row * N_EXP + tid] = slog[rr][tid];
        }
        __syncthreads();

        if (tid < 4 && rows_s[tid] >= 0)
            topk_and_write(slog[tid], rows_s[tid], vals, inds);
        __syncthreads();
    }

    // Reset counters for the next replay. Every block read g_count before
    // incrementing g_done, so the last-arriving block can safely zero both.
    if (tid == 0) {
        int old = atomicAdd(&g_done, 1);
        if (old == (int)gridDim.x - 1) {
            g_count = 0;
            g_done  = 0;
        }
    }
}

// ---------------------------------------------------------------------------
// Launch
// ---------------------------------------------------------------------------
extern "C" void kernel_launch(void* const* d_in, const int* in_sizes, int n_in,
                              void* d_out, int out_size)
{
    const float* hidden = (const float*)d_in[0];   // [16384, 2048]
    const float* weight = (const float*)d_in[1];   // [64, 2048]
    float* out = (float*)d_out;

    float* logits = out;                                 // 16384*64
    float* vals   = out + (size_t)T_TOKENS * N_EXP;      // 16384*8
    float* inds   = vals + (size_t)T_TOKENS * TOPK;      // 16384*8

    cudaFuncSetAttribute(router_fused_kernel,
                         cudaFuncAttributeMaxDynamicSharedMemorySize, SMEM_TOTAL);
    router_fused_kernel<<<T_TOKENS / BM, 256, SMEM_TOTAL>>>(
        hidden, weight, logits, vals, inds);

    router_repair_kernel<<<256, 64>>>(
        hidden, weight, logits, vals, inds);
}

// round 11
// speedup vs baseline: 5.0263x; 1.3102x over previous
#include <cuda_runtime.h>
#include <cuda_fp16.h>
#include <cstdint>
#include <math.h>

// ---------------------------------------------------------------------------
// Problem constants
// ---------------------------------------------------------------------------
#define T_TOKENS 16384
#define H_DIM    2048
#define N_EXP    64
#define TOPK     8
#define KC       64                  // fp32 k-elements per chunk
#define NCHUNK   (H_DIM / KC)        // 32
#define BM       128                 // tokens per CTA
#define GAP_THR  3.0e-5f             // marginal-row flag threshold (abs logit)

// SMEM: double-buffered fp16 tiles, 128 B per row (64 halves), swizzled.
//   per buffer: A_hi 16K | A_lo 16K | B_hi 8K | B_lo 8K = 48 KB
#define BUFSZ    49152
#define AHI_OFF(b)  ((b) * BUFSZ + 0)
#define ALO_OFF(b)  ((b) * BUFSZ + 16384)
#define BHI_OFF(b)  ((b) * BUFSZ + 32768)
#define BLO_OFF(b)  ((b) * BUFSZ + 40960)
#define SMEM_TOTAL  (2 * BUFSZ)      // 98304; epilogue reuses [0,34816) as f32

// 16-byte-granule XOR swizzle within a 128-byte row
#define SWG(row, g) ((g) ^ ((row) & 7))

// Repair kernel sizing
#define RGRID     64
#define RTHREADS  128
#define SW_STR    132                // padded floats per W smem row
#define RSM_SWBUF (64 * SW_STR)                  // floats per W buffer
#define RSM_SA    (2 * RSM_SWBUF)                // sa starts after 2 W buffers
#define RSM_SLOG  (RSM_SA + 2 * 4 * 128)         // slog after 2 A buffers
#define RSM_ROWS  (RSM_SLOG + 4 * N_EXP)         // rows_s after slog
#define REPAIR_SMEM ((RSM_ROWS + 4) * 4)         // bytes

// Compacted list of marginal rows needing exact serial-fp32 recompute.
// Zero-initialized at module load; repair kernel resets them at exit so the
// zero-at-entry invariant holds across graph replays.
__device__ int g_count;
__device__ int g_done;
__device__ int g_list[T_TOKENS];

static __device__ __forceinline__ uint32_t smem_u32(const void* p) {
    uint32_t a;
    asm("{ .reg .u64 t; cvta.to.shared.u64 t, %1; cvt.u32.u64 %0, t; }"
        : "=r"(a) : "l"(p));
    return a;
}

static __device__ __forceinline__ void ldsm4(uint32_t r[4], uint32_t addr) {
    asm volatile("ldmatrix.sync.aligned.m8n8.x4.shared.b16 {%0,%1,%2,%3}, [%4];"
                 : "=r"(r[0]), "=r"(r[1]), "=r"(r[2]), "=r"(r[3]) : "r"(addr));
}

static __device__ __forceinline__ void mma16816(
    float c[4], const uint32_t a[4], uint32_t b0, uint32_t b1)
{
    asm volatile(
        "mma.sync.aligned.m16n8k16.row.col.f32.f16.f16.f32 "
        "{%0,%1,%2,%3}, {%4,%5,%6,%7}, {%8,%9}, {%0,%1,%2,%3};"
        : "+f"(c[0]), "+f"(c[1]), "+f"(c[2]), "+f"(c[3])
        : "r"(a[0]), "r"(a[1]), "r"(a[2]), "r"(a[3]), "r"(b0), "r"(b1));
}

static __device__ __forceinline__ void cpa16(uint32_t dst, const void* src) {
    asm volatile("cp.async.ca.shared.global [%0], [%1], 16;"
                 :: "r"(dst), "l"(src) : "memory");
}
#define CP_COMMIT() asm volatile("cp.async.commit_group;" ::: "memory")
#define CP_WAIT(n)  asm volatile("cp.async.wait_group %0;" :: "n"(n) : "memory")

// Split 8 fp32 into fp16 hi (16 B) and fp16 lo (16 B).
static __device__ __forceinline__ void cvt8(
    float4 p, float4 q, uint4& hi, uint4& lo)
{
    __half2 h0 = __floats2half2_rn(p.x, p.y);
    __half2 h1 = __floats2half2_rn(p.z, p.w);
    __half2 h2 = __floats2half2_rn(q.x, q.y);
    __half2 h3 = __floats2half2_rn(q.z, q.w);
    float2 f0 = __half22float2(h0), f1 = __half22float2(h1);
    float2 f2 = __half22float2(h2), f3 = __half22float2(h3);
    __half2 l0 = __floats2half2_rn(p.x - f0.x, p.y - f0.y);
    __half2 l1 = __floats2half2_rn(p.z - f1.x, p.w - f1.y);
    __half2 l2 = __floats2half2_rn(q.x - f2.x, q.y - f2.y);
    __half2 l3 = __floats2half2_rn(q.z - f3.x, q.w - f3.y);
    hi.x = *(uint32_t*)&h0; hi.y = *(uint32_t*)&h1;
    hi.z = *(uint32_t*)&h2; hi.w = *(uint32_t*)&h3;
    lo.x = *(uint32_t*)&l0; lo.y = *(uint32_t*)&l1;
    lo.z = *(uint32_t*)&l2; lo.w = *(uint32_t*)&l3;
}

// Shared top-8 + renormalized softmax writer (ties -> lower index).
static __device__ __forceinline__ void topk_and_write(
    const float* v_in, int row, float* vals, float* inds)
{
    float v[N_EXP];
#pragma unroll
    for (int j = 0; j < N_EXP; j++) v[j] = v_in[j];

    float tv[TOPK]; int ti[TOPK];
#pragma unroll
    for (int it = 0; it < TOPK; it++) {
        float bv = -INFINITY; int bi = 0;
#pragma unroll
        for (int j = 0; j < N_EXP; j++)
            if (v[j] > bv) { bv = v[j]; bi = j; }
        tv[it] = bv; ti[it] = bi;
        v[bi] = -INFINITY;
    }

    const float m = tv[0];
    float e[TOPK], s = 0.0f;
#pragma unroll
    for (int i = 0; i < TOPK; i++) { e[i] = expf(tv[i] - m); s += e[i]; }
    const float inv = 1.0f / s;

    *(float4*)(vals + (size_t)row * TOPK) =
        make_float4(e[0]*inv, e[1]*inv, e[2]*inv, e[3]*inv);
    *(float4*)(vals + (size_t)row * TOPK + 4) =
        make_float4(e[4]*inv, e[5]*inv, e[6]*inv, e[7]*inv);
    *(float4*)(inds + (size_t)row * TOPK) =
        make_float4((float)ti[0], (float)ti[1], (float)ti[2], (float)ti[3]);
    *(float4*)(inds + (size_t)row * TOPK + 4) =
        make_float4((float)ti[4], (float)ti[5], (float)ti[6], (float)ti[7]);
}

// ---------------------------------------------------------------------------
// Fused kernel: logits = A @ W^T via HMMA fp16 split (dual accumulators),
// double-buffered smem, 1 sync per chunk, + top-8 + flagging.
// ---------------------------------------------------------------------------
__global__ void __launch_bounds__(256, 1)
router_fused_kernel(const float* __restrict__ A,   // [T, H]
                    const float* __restrict__ W,   // [E, H]
                    float* __restrict__ logits,    // [T, E]
                    float* __restrict__ vals,      // [T, 8]
                    float* __restrict__ inds)      // [T, 8]
{
    extern __shared__ char smem[];
    const uint32_t sb = smem_u32(smem);
    const int tid  = threadIdx.x;
    const int wid  = tid >> 5;
    const int lane = tid & 31;
    const int blockRow = blockIdx.x * BM;
    const int mrow = wid * 16;

    float acc[8][4];     // hi*hi   (full magnitude)
    float acc2[8][4];    // hi*lo + lo*hi   (~2^-11 magnitude)
#pragma unroll
    for (int t = 0; t < 8; t++)
#pragma unroll
        for (int j = 0; j < 4; j++) { acc[t][j] = 0.0f; acc2[t][j] = 0.0f; }

    const float* Abase = A + (size_t)blockRow * H_DIM;

    const int ldRowA[4] = { (tid + 0*256) >> 3, (tid + 1*256) >> 3,
                            (tid + 2*256) >> 3, (tid + 3*256) >> 3 };
    const int ldG = tid & 7;

    float4 pa[4][2], pw[2][2];

    // ---- prologue: LDG chunk 0, convert+store into buffer 0
#pragma unroll
    for (int t = 0; t < 4; t++) {
        const float* p = Abase + (size_t)ldRowA[t] * H_DIM + ldG * 8;
        pa[t][0] = *(const float4*)p;
        pa[t][1] = *(const float4*)(p + 4);
    }
#pragma unroll
    for (int t = 0; t < 2; t++) {
        int row = (tid + t * 256) >> 3;
        const float* p = W + (size_t)row * H_DIM + ldG * 8;
        pw[t][0] = *(const float4*)p;
        pw[t][1] = *(const float4*)(p + 4);
    }
#pragma unroll
    for (int t = 0; t < 4; t++) {
        uint4 hi, lo;
        cvt8(pa[t][0], pa[t][1], hi, lo);
        int off = ldRowA[t] * 128 + SWG(ldRowA[t], ldG) * 16;
        *(uint4*)(smem + AHI_OFF(0) + off) = hi;
        *(uint4*)(smem + ALO_OFF(0) + off) = lo;
    }
#pragma unroll
    for (int t = 0; t < 2; t++) {
        int row = (tid + t * 256) >> 3;
        uint4 hi, lo;
        cvt8(pw[t][0], pw[t][1], hi, lo);
        int off = row * 128 + SWG(row, ldG) * 16;
        *(uint4*)(smem + BHI_OFF(0) + off) = hi;
        *(uint4*)(smem + BLO_OFF(0) + off) = lo;
    }

    const int lj  = lane >> 3;
    const int lrr = lane & 7;
    const int jr  = (lj & 1) * 8 + lrr;
    const int jg  = lj >> 1;

    for (int c = 0; c < NCHUNK; c++) {
        const int buf = c & 1;

        // ---- issue next chunk's global loads (consumed after MMA)
        if (c + 1 < NCHUNK) {
            const float* Ab = Abase + (c + 1) * KC;
            const float* Wb = W + (c + 1) * KC;
#pragma unroll
            for (int t = 0; t < 4; t++) {
                const float* p = Ab + (size_t)ldRowA[t] * H_DIM + ldG * 8;
                pa[t][0] = *(const float4*)p;
                pa[t][1] = *(const float4*)(p + 4);
            }
#pragma unroll
            for (int t = 0; t < 2; t++) {
                int row = (tid + t * 256) >> 3;
                const float* p = Wb + (size_t)row * H_DIM + ldG * 8;
                pw[t][0] = *(const float4*)p;
                pw[t][1] = *(const float4*)(p + 4);
            }
        }

        __syncthreads();   // all warps' stores into buf are complete

        // ---- MMA over buf: 4 k16-steps
#pragma unroll
        for (int ks = 0; ks < 4; ks++) {
            const int gk = ks * 2;

            uint32_t ah[4], al[4];
            {
                int arow = mrow + jr;
                int ag   = gk + jg;
                uint32_t off = arow * 128 + SWG(arow, ag) * 16;
                ldsm4(ah, sb + AHI_OFF(buf) + off);
                ldsm4(al, sb + ALO_OFF(buf) + off);
            }

            uint32_t bh[8][2], bl[8][2];
#pragma unroll
            for (int p = 0; p < 4; p++) {
                int brow = p * 16 + jr;
                int bg   = gk + jg;
                uint32_t off = brow * 128 + SWG(brow, bg) * 16;
                uint32_t r[4];
                ldsm4(r, sb + BHI_OFF(buf) + off);
                bh[2*p][0] = r[0]; bh[2*p][1] = r[2];
                bh[2*p+1][0] = r[1]; bh[2*p+1][1] = r[3];
                ldsm4(r, sb + BLO_OFF(buf) + off);
                bl[2*p][0] = r[0]; bl[2*p][1] = r[2];
                bl[2*p+1][0] = r[1]; bl[2*p+1][1] = r[3];
            }

#pragma unroll
            for (int t = 0; t < 8; t++) {
                mma16816(acc[t],  ah, bh[t][0], bh[t][1]);   // hi*hi -> acc
                mma16816(acc2[t], ah, bl[t][0], bl[t][1]);   // hi*lo -> acc2
                mma16816(acc2[t], al, bh[t][0], bh[t][1]);   // lo*hi -> acc2
            }
        }

        // ---- convert + store next chunk into the other buffer
        if (c + 1 < NCHUNK) {
            const int nbuf = buf ^ 1;
#pragma unroll
            for (int t = 0; t < 4; t++) {
                uint4 hi, lo;
                cvt8(pa[t][0], pa[t][1], hi, lo);
                int off = ldRowA[t] * 128 + SWG(ldRowA[t], ldG) * 16;
                *(uint4*)(smem + AHI_OFF(nbuf) + off) = hi;
                *(uint4*)(smem + ALO_OFF(nbuf) + off) = lo;
            }
#pragma unroll
            for (int t = 0; t < 2; t++) {
                int row = (tid + t * 256) >> 3;
                uint4 hi, lo;
                cvt8(pw[t][0], pw[t][1], hi, lo);
                int off = row * 128 + SWG(row, ldG) * 16;
                *(uint4*)(smem + BHI_OFF(nbuf) + off) = hi;
                *(uint4*)(smem + BLO_OFF(nbuf) + off) = lo;
            }
        }
    }

    // Fold the small-term accumulator in once.
#pragma unroll
    for (int t = 0; t < 8; t++)
#pragma unroll
        for (int j = 0; j < 4; j++) acc[t][j] += acc2[t][j];

    __syncthreads();   // all warps done with the final MMA buffer

    // ---------------- Epilogue ----------------
    float* lsm = (float*)smem;   // [128][68] f32 (34816 B)
    {
        const int group = lane >> 2, tig = lane & 3;
#pragma unroll
        for (int t = 0; t < 8; t++) {
            int col = t * 8 + 2 * tig;
            *(float2*)&lsm[(mrow + group)     * 68 + col] =
                make_float2(acc[t][0], acc[t][1]);
            *(float2*)&lsm[(mrow + group + 8) * 68 + col] =
                make_float2(acc[t][2], acc[t][3]);
        }
    }
    __syncthreads();

    // Coalesced logits store
#pragma unroll
    for (int t = 0; t < 8; t++) {
        int i = tid + t * 256;
        int row = i >> 4, q = i & 15;
        float4 v = *(float4*)&lsm[row * 68 + q * 4];
        *(float4*)&logits[(size_t)(blockRow + row) * N_EXP + q * 4] = v;
    }

    // Top-8 + renorm softmax + marginal-row flag: threads 0..127, one row each
    if (tid < BM) {
        const int row = blockRow + tid;
        float v[N_EXP];
#pragma unroll
        for (int j = 0; j < N_EXP; j++) v[j] = lsm[tid * 68 + j];

        float tv[TOPK + 1]; int ti[TOPK];
#pragma unroll
        for (int it = 0; it < TOPK; it++) {
            float bv = -INFINITY; int bi = 0;
#pragma unroll
            for (int j = 0; j < N_EXP; j++)
                if (v[j] > bv) { bv = v[j]; bi = j; }
            tv[it] = bv; ti[it] = bi;
            v[bi] = -INFINITY;
        }
        {
            float bv = -INFINITY;
#pragma unroll
            for (int j = 0; j < N_EXP; j++) bv = fmaxf(bv, v[j]);
            tv[TOPK] = bv;
        }

        float min_gap = INFINITY;
#pragma unroll
        for (int i = 0; i < TOPK; i++) min_gap = fminf(min_gap, tv[i] - tv[i + 1]);
        if (min_gap < GAP_THR) {
            int idx = atomicAdd(&g_count, 1);
            g_list[idx] = row;
        }

        const float m = tv[0];
        float e[TOPK], s = 0.0f;
#pragma unroll
        for (int i = 0; i < TOPK; i++) { e[i] = expf(tv[i] - m); s += e[i]; }
        const float inv = 1.0f / s;

        *(float4*)(vals + (size_t)row * TOPK) =
            make_float4(e[0]*inv, e[1]*inv, e[2]*inv, e[3]*inv);
        *(float4*)(vals + (size_t)row * TOPK + 4) =
            make_float4(e[4]*inv, e[5]*inv, e[6]*inv, e[7]*inv);
        *(float4*)(inds + (size_t)row * TOPK) =
            make_float4((float)ti[0], (float)ti[1], (float)ti[2], (float)ti[3]);
        *(float4*)(inds + (size_t)row * TOPK + 4) =
            make_float4((float)ti[4], (float)ti[5], (float)ti[6], (float)ti[7]);
    }
}

// ---------------------------------------------------------------------------
// Repair kernel v2: serial-in-k fp32 recompute of marginal rows.
// 128 threads: thread = (expert e, row-pair p); 2 chains per thread.
// cp.async double-buffered W/A staging; float4 LDS (132-float padded rows).
// Accumulation order k = 0..2047 strictly serial -> bitwise-stable results.
// ---------------------------------------------------------------------------
__global__ void __launch_bounds__(RTHREADS)
router_repair_kernel(const float* __restrict__ A,
                     const float* __restrict__ W,
                     float* __restrict__ logits,
                     float* __restrict__ vals,
                     float* __restrict__ inds)
{
    extern __shared__ float rs[];
    float* slog   = rs + RSM_SLOG;        // [4][64]
    int*   rows_s = (int*)(rs + RSM_ROWS);

    const uint32_t sbase = smem_u32(rs);
    const int tid = threadIdx.x;
    const int e   = tid & 63;             // expert
    const int pr  = tid >> 6;             // row-pair: rows 2pr, 2pr+1

    const int count = g_count;
    const int ngroups = (count + 3) >> 2;

    for (int g = blockIdx.x; g < ngroups; g += gridDim.x) {
        __syncthreads();                  // protect rows_s/slog reuse
        if (tid < 4) {
            int i = g * 4 + tid;
            rows_s[tid] = (i < count) ? g_list[i] : -1;
        }
        __syncthreads();

        // --- prefetch helper (inlined twice): chunk c into buffer b
        // W: 2048 float4 / 128 thr = 16 each; A: 128 float4 / 128 thr = 1 each
#define RP_PREFETCH(c, b) do {                                               \
        const float* Wc = W + (c) * 128;                                     \
        uint32_t swb = sbase + (b) * (RSM_SWBUF * 4);                        \
        _Pragma("unroll")                                                    \
        for (int j = 0; j < 16; j++) {                                       \
            int i = tid + RTHREADS * j;                                      \
            int row = i >> 5, q = i & 31;                                    \
            cpa16(swb + (row * SW_STR + q * 4) * 4,                          \
                  Wc + (size_t)row * H_DIM + q * 4);                         \
        }                                                                    \
        {                                                                    \
            int rr = tid >> 5, q = tid & 31;                                 \
            int row = rows_s[rr]; if (row < 0) row = 0;                      \
            uint32_t sab = sbase + (RSM_SA + (b) * 512 + rr * 128 + q * 4) * 4; \
            cpa16(sab, A + (size_t)row * H_DIM + (c) * 128 + q * 4);         \
        }                                                                    \
        CP_COMMIT();                                                         \
    } while (0)

        RP_PREFETCH(0, 0);

        float acc0 = 0.0f, acc1 = 0.0f;

        for (int c = 0; c < 16; c++) {
            const int buf = c & 1;
            if (c + 1 < 16) {
                RP_PREFETCH(c + 1, buf ^ 1);
                CP_WAIT(1);
            } else {
                CP_WAIT(0);
            }
            __syncthreads();              // chunk c visible to all threads

            const float* swr = rs + buf * RSM_SWBUF + e * SW_STR;
            const float* sa0 = rs + RSM_SA + buf * 512 + (2 * pr) * 128;
            const float* sa1 = sa0 + 128;

#pragma unroll
            for (int k4 = 0; k4 < 32; k4++) {
                float4 w4 = *(const float4*)(swr + k4 * 4);
                float4 a0 = *(const float4*)(sa0 + k4 * 4);
                float4 a1 = *(const float4*)(sa1 + k4 * 4);
                acc0 = fmaf(a0.x, w4.x, acc0);
                acc0 = fmaf(a0.y, w4.y, acc0);
                acc0 = fmaf(a0.z, w4.z, acc0);
                acc0 = fmaf(a0.w, w4.w, acc0);
                acc1 = fmaf(a1.x, w4.x, acc1);
                acc1 = fmaf(a1.y, w4.y, acc1);
                acc1 = fmaf(a1.z, w4.z, acc1);
                acc1 = fmaf(a1.w, w4.w, acc1);
            }
            __syncthreads();              // all done reading buf before reuse
        }

        slog[(2 * pr)     * N_EXP + e] = acc0;
        slog[(2 * pr + 1) * N_EXP + e] = acc1;
        {
            int r0 = rows_s[2 * pr];
            int r1 = rows_s[2 * pr + 1];
            if (r0 >= 0) logits[(size_t)r0 * N_EXP + e] = acc0;
            if (r1 >= 0) logits[(size_t)r1 * N_EXP + e] = acc1;
        }
        __syncthreads();

        if (tid < 4 && rows_s[tid] >= 0)
            topk_and_write(slog + tid * N_EXP, rows_s[tid], vals, inds);
#undef RP_PREFETCH
    }

    // Reset counters for the next replay. Every block read g_count before
    // incrementing g_done, so the last-arriving block can safely zero both.
    if (tid == 0) {
        int old = atomicAdd(&g_done, 1);
        if (old == (int)gridDim.x - 1) {
            g_count = 0;
            g_done  = 0;
        }
    }
}

// ---------------------------------------------------------------------------
// Launch
// ---------------------------------------------------------------------------
extern "C" void kernel_launch(void* const* d_in, const int* in_sizes, int n_in,
                              void* d_out, int out_size)
{
    const float* hidden = (const float*)d_in[0];   // [16384, 2048]
    const float* weight = (const float*)d_in[1];   // [64, 2048]
    float* out = (float*)d_out;

    float* logits = out;                                 // 16384*64
    float* vals   = out + (size_t)T_TOKENS * N_EXP;      // 16384*8
    float* inds   = vals + (size_t)T_TOKENS * TOPK;      // 16384*8

    cudaFuncSetAttribute(router_fused_kernel,
                         cudaFuncAttributeMaxDynamicSharedMemorySize, SMEM_TOTAL);
    router_fused_kernel<<<T_TOKENS / BM, 256, SMEM_TOTAL>>>(
        hidden, weight, logits, vals, inds);

    cudaFuncSetAttribute(router_repair_kernel,
                         cudaFuncAttributeMaxDynamicSharedMemorySize, REPAIR_SMEM);
    router_repair_kernel<<<RGRID, RTHREADS, REPAIR_SMEM>>>(
        hidden, weight, logits, vals, inds);
}